// round 1
// baseline (speedup 1.0000x reference)
#include <cuda_runtime.h>

#define HH 128
#define NMAX 50000
#define BN_EPS 1e-5f

// ---------------- scratch (no allocations allowed) ----------------
__device__ float g_agg[NMAX * HH];
__device__ float g_z[NMAX * HH];
__device__ float g_hA[NMAX * HH];
__device__ float g_hB[NMAX * HH];
__device__ float g_stats[2 * HH];   // [0:128) col sums, [128:256) col sumsq
__device__ float g_scale[HH];       // gamma * rstd
__device__ float g_shift[HH];       // beta - mu * gamma * rstd

// ---------------- edge scatter: agg[dst] += h[src] ----------------
// warp per edge, lane l handles float4 chunk l (128 floats = 32 float4)
__global__ void scatter_kernel(const float4* __restrict__ h,
                               const int* __restrict__ src,
                               const int* __restrict__ dst,
                               float4* __restrict__ agg, int E) {
    int t = blockIdx.x * blockDim.x + threadIdx.x;
    int e = t >> 5;
    int l = t & 31;
    if (e >= E) return;
    int s = src[e];
    int d = dst[e];
    float4 v = h[(size_t)s * 32 + l];
    atomicAdd(&agg[(size_t)d * 32 + l], v);
}

// ---------------- fused GEMM (128-wide), BM=128 BN=128 BK=16, 8x8 microtile ----
// MODE 0: A = hin + agg ; out = A@W + bias              (pre-BN linear, stores z)
// MODE 1: A = relu(z*scale + shift) ; out = relu(A@W+b) (BN+ReLU fused on load)
template <int MODE>
__global__ __launch_bounds__(256) void gemm128(
    const float* __restrict__ A1, const float* __restrict__ A2,
    const float* __restrict__ W, const float* __restrict__ bias,
    float* __restrict__ out, int nrows) {
    __shared__ float As[16][132];
    __shared__ float Bs[16][128];

    int block_row = blockIdx.x * 128;
    int tid = threadIdx.x;
    int tr = tid >> 4;   // 0..15
    int tc = tid & 15;   // 0..15

    float acc[8][8] = {};

    for (int kt = 0; kt < 8; kt++) {
        // ---- load A tile (128 rows x 16 k), fused transform ----
#pragma unroll
        for (int it = 0; it < 2; it++) {
            int id = tid + it * 256;      // 0..511 float4 tasks
            int m = id >> 2;              // row in tile
            int k4 = id & 3;              // which float4 within 16 k's
            int row = block_row + m;
            float4 v = make_float4(0.f, 0.f, 0.f, 0.f);
            if (row < nrows) {
                int gidx = row * HH + kt * 16 + k4 * 4;
                v = *reinterpret_cast<const float4*>(&A1[gidx]);
                if (MODE == 0) {
                    float4 w = *reinterpret_cast<const float4*>(&A2[gidx]);
                    v.x += w.x; v.y += w.y; v.z += w.z; v.w += w.w;
                } else {
                    int k = kt * 16 + k4 * 4;
                    v.x = fmaxf(fmaf(v.x, g_scale[k + 0], g_shift[k + 0]), 0.f);
                    v.y = fmaxf(fmaf(v.y, g_scale[k + 1], g_shift[k + 1]), 0.f);
                    v.z = fmaxf(fmaf(v.z, g_scale[k + 2], g_shift[k + 2]), 0.f);
                    v.w = fmaxf(fmaf(v.w, g_scale[k + 3], g_shift[k + 3]), 0.f);
                }
            }
            As[k4 * 4 + 0][m] = v.x;
            As[k4 * 4 + 1][m] = v.y;
            As[k4 * 4 + 2][m] = v.z;
            As[k4 * 4 + 3][m] = v.w;
        }
        // ---- load B tile (16 k x 128 cols), row-major copy ----
#pragma unroll
        for (int it = 0; it < 2; it++) {
            int id = tid + it * 256;
            int k = id >> 5;              // 0..15
            int n4 = id & 31;
            float4 v = *reinterpret_cast<const float4*>(
                &W[(kt * 16 + k) * HH + n4 * 4]);
            *reinterpret_cast<float4*>(&Bs[k][n4 * 4]) = v;
        }
        __syncthreads();

#pragma unroll
        for (int kk = 0; kk < 16; kk++) {
            float a[8], b[8];
#pragma unroll
            for (int i = 0; i < 8; i++) a[i] = As[kk][tr * 8 + i];
#pragma unroll
            for (int j = 0; j < 8; j++) b[j] = Bs[kk][tc * 8 + j];
#pragma unroll
            for (int i = 0; i < 8; i++)
#pragma unroll
                for (int j = 0; j < 8; j++)
                    acc[i][j] = fmaf(a[i], b[j], acc[i][j]);
        }
        __syncthreads();
    }

    // ---- epilogue ----
#pragma unroll
    for (int i = 0; i < 8; i++) {
        int row = block_row + tr * 8 + i;
        if (row >= nrows) break;
#pragma unroll
        for (int j = 0; j < 8; j++) {
            int col = tc * 8 + j;
            float v = acc[i][j] + bias[col];
            if (MODE == 1) v = fmaxf(v, 0.f);
            out[row * HH + col] = v;
        }
    }
}

// ---------------- BN column stats: sum and sumsq per feature ----------------
__global__ void stats_kernel(const float* __restrict__ z, int nrows) {
    int col = threadIdx.x;  // 0..127
    float s = 0.f, sq = 0.f;
    for (int r = blockIdx.x; r < nrows; r += gridDim.x) {
        float v = z[r * HH + col];
        s += v;
        sq = fmaf(v, v, sq);
    }
    atomicAdd(&g_stats[col], s);
    atomicAdd(&g_stats[HH + col], sq);
}

__global__ void finalize_kernel(const float* __restrict__ gamma,
                                const float* __restrict__ beta, float inv_n) {
    int c = threadIdx.x;
    float mu = g_stats[c] * inv_n;
    float var = fmaf(-mu, mu, g_stats[HH + c] * inv_n);
    float rstd = rsqrtf(var + BN_EPS);
    float sc = gamma[c] * rstd;
    g_scale[c] = sc;
    g_shift[c] = fmaf(-mu, sc, beta[c]);
}

// ---------------- segment-CSR readout: out[g] = sum h[ptr[g]:ptr[g+1]] -------
__global__ void readout_kernel(const float* __restrict__ h,
                               const int* __restrict__ ptr,
                               float* __restrict__ out) {
    int g = blockIdx.x;
    int c = threadIdx.x;
    int s = ptr[g], e = ptr[g + 1];
    float acc = 0.f;
    for (int r = s; r < e; r++) acc += h[r * HH + c];
    out[g * HH + c] = acc;
}

// ---------------- host launch ----------------
extern "C" void kernel_launch(void* const* d_in, const int* in_sizes, int n_in,
                              void* d_out, int out_size) {
    const float* x   = (const float*)d_in[0];
    const int* src   = (const int*)d_in[1];
    const int* dst   = (const int*)d_in[2];
    const int* ptr   = (const int*)d_in[3];
    int E = in_sizes[1];
    int N = in_sizes[0] / HH;
    int G = in_sizes[3] - 1;
    float* out = (float*)d_out;

    float *agg, *z, *hA, *hB, *stats;
    cudaGetSymbolAddress((void**)&agg, g_agg);
    cudaGetSymbolAddress((void**)&z, g_z);
    cudaGetSymbolAddress((void**)&hA, g_hA);
    cudaGetSymbolAddress((void**)&hB, g_hB);
    cudaGetSymbolAddress((void**)&stats, g_stats);

    int gemm_blocks = (N + 127) / 128;
    long long scat_threads = (long long)E * 32;
    int scat_blocks = (int)((scat_threads + 255) / 256);

    auto layer = [&](const float* hin, float* hout, int base) {
        const float* wa = (const float*)d_in[base + 0];
        const float* ba = (const float*)d_in[base + 1];
        const float* ga = (const float*)d_in[base + 2];
        const float* be = (const float*)d_in[base + 3];
        const float* wb = (const float*)d_in[base + 4];
        const float* bb = (const float*)d_in[base + 5];

        cudaMemsetAsync(agg, 0, (size_t)N * HH * sizeof(float));
        cudaMemsetAsync(stats, 0, 2 * HH * sizeof(float));
        scatter_kernel<<<scat_blocks, 256>>>((const float4*)hin, src, dst,
                                             (float4*)agg, E);
        gemm128<0><<<gemm_blocks, 256>>>(hin, agg, wa, ba, z, N);
        stats_kernel<<<256, 128>>>(z, N);
        finalize_kernel<<<1, 128>>>(ga, be, 1.0f / (float)N);
        gemm128<1><<<gemm_blocks, 256>>>(z, nullptr, wb, bb, hout, N);
    };

    layer(x, hA, 4);
    layer(hA, hB, 10);
    layer(hB, hA, 16);

    readout_kernel<<<G, 128>>>(hA, ptr, out);
}

// round 3
// speedup vs baseline: 1.6767x; 1.6767x over previous
#include <cuda_runtime.h>

#define HH 128
#define NMAX 50000
#define EMAX 800000
#define BN_EPS 1e-5f

// ---------------- scratch (no allocations allowed) ----------------
__device__ float g_agg[NMAX * HH];
__device__ float g_z[NMAX * HH];
__device__ float g_hA[NMAX * HH];
__device__ float g_hB[NMAX * HH];
__device__ float g_stats[2 * HH];   // [0:128) col sums, [128:256) col sumsq
__device__ float g_scale[HH];       // gamma * rstd
__device__ float g_shift[HH];       // beta - mu * gamma * rstd
__device__ int   g_deg[NMAX];
__device__ int   g_cursor[NMAX];
__device__ int   g_rowstart[NMAX + 1];
__device__ int   g_csr[EMAX];

// ---------------- CSR build ----------------
__global__ void count_kernel(const int* __restrict__ dst, int* __restrict__ deg, int E) {
    int e = blockIdx.x * blockDim.x + threadIdx.x;
    if (e < E) atomicAdd(&deg[dst[e]], 1);
}

// single-block exclusive scan (1024 threads, warp-shuffle based)
__global__ void scan_kernel(const int* __restrict__ deg, int* __restrict__ rowstart, int n) {
    __shared__ int warpsum[32];
    __shared__ int s_total;
    __shared__ int s_carry;
    int tid = threadIdx.x, lane = tid & 31, wid = tid >> 5;
    if (tid == 0) s_carry = 0;
    __syncthreads();
    for (int base = 0; base < n; base += 1024) {
        int i = base + tid;
        int v = (i < n) ? deg[i] : 0;
        int incl = v;
#pragma unroll
        for (int off = 1; off < 32; off <<= 1) {
            int t = __shfl_up_sync(0xffffffff, incl, off);
            if (lane >= off) incl += t;
        }
        if (lane == 31) warpsum[wid] = incl;
        __syncthreads();
        if (wid == 0) {
            int w = warpsum[lane];
            int wincl = w;
#pragma unroll
            for (int off = 1; off < 32; off <<= 1) {
                int t = __shfl_up_sync(0xffffffff, wincl, off);
                if (lane >= off) wincl += t;
            }
            warpsum[lane] = wincl - w;       // exclusive warp offset
            if (lane == 31) s_total = wincl; // block total
        }
        __syncthreads();
        int carry = s_carry;
        if (i < n) rowstart[i] = carry + warpsum[wid] + incl - v;
        __syncthreads();
        if (tid == 0) s_carry = carry + s_total;
    }
    __syncthreads();
    if (tid == 0) rowstart[n] = s_carry;
}

__global__ void fill_kernel(const int* __restrict__ src, const int* __restrict__ dst,
                            const int* __restrict__ rowstart, int* __restrict__ cursor,
                            int* __restrict__ csr, int E) {
    int e = blockIdx.x * blockDim.x + threadIdx.x;
    if (e >= E) return;
    int d = dst[e];
    int base = __ldg(&rowstart[d]);          // issue early; overlaps atomic latency
    int p = atomicAdd(&cursor[d], 1);
    csr[base + p] = src[e];
}

// ---------------- aggregate: agg[i] = h[i] + sum_{j in N_in(i)} h[j] ---------
// warp per node; lane handles one float4 (32 lanes * 4 = 128 floats)
__global__ void aggregate_kernel(const float4* __restrict__ h,
                                 const int* __restrict__ rowstart,
                                 const int* __restrict__ csr,
                                 float4* __restrict__ agg, int N) {
    int warp = (blockIdx.x * blockDim.x + threadIdx.x) >> 5;
    int lane = threadIdx.x & 31;
    if (warp >= N) return;
    int s0 = rowstart[warp], s1 = rowstart[warp + 1];
    float4 acc = __ldg(&h[(size_t)warp * 32 + lane]);
    int j = s0;
    for (; j + 2 <= s1; j += 2) {
        int sa = __ldg(&csr[j]);
        int sb = __ldg(&csr[j + 1]);
        float4 va = __ldg(&h[(size_t)sa * 32 + lane]);
        float4 vb = __ldg(&h[(size_t)sb * 32 + lane]);
        acc.x += va.x + vb.x; acc.y += va.y + vb.y;
        acc.z += va.z + vb.z; acc.w += va.w + vb.w;
    }
    if (j < s1) {
        int sa = __ldg(&csr[j]);
        float4 va = __ldg(&h[(size_t)sa * 32 + lane]);
        acc.x += va.x; acc.y += va.y; acc.z += va.z; acc.w += va.w;
    }
    agg[(size_t)warp * 32 + lane] = acc;
}

// ---------------- fused GEMM (128-wide), BM=128 BN=128 BK=16, 8x8 microtile --
// MODE 0: out = A@W + bias (stores z) ; fused BN column stats -> g_stats
// MODE 1: A' = relu(A*scale+shift) ; out = relu(A'@W + bias)
template <int MODE>
__global__ __launch_bounds__(256) void gemm128(
    const float* __restrict__ A1,
    const float* __restrict__ W, const float* __restrict__ bias,
    float* __restrict__ out, int nrows) {
    __shared__ float As[16][132];
    __shared__ float Bs[16][132];
    __shared__ float sh_scale[HH];
    __shared__ float sh_shift[HH];

    int block_row = blockIdx.x * 128;
    int tid = threadIdx.x;
    int tr = tid >> 4;   // 0..15
    int tc = tid & 15;   // 0..15

    if (MODE == 1) {
        if (tid < 128) {
            sh_scale[tid] = g_scale[tid];
            sh_shift[tid] = g_shift[tid];
        }
        __syncthreads();
    }

    float acc[8][8] = {};

    for (int kt = 0; kt < 8; kt++) {
        // ---- load A tile (128 rows x 16 k), fused transform ----
#pragma unroll
        for (int it = 0; it < 2; it++) {
            int id = tid + it * 256;      // 0..511 float4 tasks
            int m = id >> 2;              // row in tile
            int k4 = id & 3;              // which float4 within 16 k's
            int row = block_row + m;
            float4 v = make_float4(0.f, 0.f, 0.f, 0.f);
            if (row < nrows) {
                int gidx = row * HH + kt * 16 + k4 * 4;
                v = *reinterpret_cast<const float4*>(&A1[gidx]);
                if (MODE == 1) {
                    int k = kt * 16 + k4 * 4;
                    v.x = fmaxf(fmaf(v.x, sh_scale[k + 0], sh_shift[k + 0]), 0.f);
                    v.y = fmaxf(fmaf(v.y, sh_scale[k + 1], sh_shift[k + 1]), 0.f);
                    v.z = fmaxf(fmaf(v.z, sh_scale[k + 2], sh_shift[k + 2]), 0.f);
                    v.w = fmaxf(fmaf(v.w, sh_scale[k + 3], sh_shift[k + 3]), 0.f);
                }
            }
            As[k4 * 4 + 0][m] = v.x;
            As[k4 * 4 + 1][m] = v.y;
            As[k4 * 4 + 2][m] = v.z;
            As[k4 * 4 + 3][m] = v.w;
        }
        // ---- load B tile (16 k x 128 cols) ----
#pragma unroll
        for (int it = 0; it < 2; it++) {
            int id = tid + it * 256;
            int k = id >> 5;              // 0..15
            int n4 = id & 31;
            float4 v = *reinterpret_cast<const float4*>(
                &W[(kt * 16 + k) * HH + n4 * 4]);
            *reinterpret_cast<float4*>(&Bs[k][n4 * 4]) = v;
        }
        __syncthreads();

#pragma unroll
        for (int kk = 0; kk < 16; kk++) {
            float a[8], b[8];
#pragma unroll
            for (int i = 0; i < 8; i++) a[i] = As[kk][tr * 8 + i];
#pragma unroll
            for (int j = 0; j < 8; j++) b[j] = Bs[kk][tc * 8 + j];
#pragma unroll
            for (int i = 0; i < 8; i++)
#pragma unroll
                for (int j = 0; j < 8; j++)
                    acc[i][j] = fmaf(a[i], b[j], acc[i][j]);
        }
        __syncthreads();
    }

    // ---- epilogue: store out (vectorized), accumulate column stats (MODE 0) --
    float bcol[8];
#pragma unroll
    for (int j = 0; j < 8; j++) bcol[j] = bias[tc * 8 + j];

    float s[8] = {}, sq[8] = {};
#pragma unroll
    for (int i = 0; i < 8; i++) {
        int row = block_row + tr * 8 + i;
        if (row < nrows) {
            float v[8];
#pragma unroll
            for (int j = 0; j < 8; j++) {
                float t = acc[i][j] + bcol[j];
                if (MODE == 1) t = fmaxf(t, 0.f);
                v[j] = t;
                if (MODE == 0) {
                    s[j] += t;
                    sq[j] = fmaf(t, t, sq[j]);
                }
            }
            float4* op = reinterpret_cast<float4*>(&out[row * HH + tc * 8]);
            op[0] = make_float4(v[0], v[1], v[2], v[3]);
            op[1] = make_float4(v[4], v[5], v[6], v[7]);
        }
    }

    if (MODE == 0) {
        // shared transpose-reduce: partial[tr][col] then 128 threads sum 16 rows
#pragma unroll
        for (int j = 0; j < 8; j++) {
            As[tr][tc * 8 + j] = s[j];
            Bs[tr][tc * 8 + j] = sq[j];
        }
        __syncthreads();
        if (tid < 128) {
            float ts = 0.f, tq = 0.f;
#pragma unroll
            for (int r = 0; r < 16; r++) {
                ts += As[r][tid];
                tq += Bs[r][tid];
            }
            atomicAdd(&g_stats[tid], ts);
            atomicAdd(&g_stats[HH + tid], tq);
        }
    }
}

__global__ void finalize_kernel(const float* __restrict__ gamma,
                                const float* __restrict__ beta, float inv_n) {
    int c = threadIdx.x;
    float mu = g_stats[c] * inv_n;
    float var = fmaf(-mu, mu, g_stats[HH + c] * inv_n);
    float rstd = rsqrtf(var + BN_EPS);
    float sc = gamma[c] * rstd;
    g_scale[c] = sc;
    g_shift[c] = fmaf(-mu, sc, beta[c]);
}

// ---------------- segment-CSR readout ----------------
__global__ void readout_kernel(const float* __restrict__ h,
                               const int* __restrict__ ptr,
                               float* __restrict__ out) {
    int g = blockIdx.x;
    int c = threadIdx.x;
    int s = ptr[g], e = ptr[g + 1];
    float acc = 0.f;
    for (int r = s; r < e; r++) acc += h[r * HH + c];
    out[g * HH + c] = acc;
}

// ---------------- host launch ----------------
extern "C" void kernel_launch(void* const* d_in, const int* in_sizes, int n_in,
                              void* d_out, int out_size) {
    const float* x   = (const float*)d_in[0];
    const int* src   = (const int*)d_in[1];
    const int* dst   = (const int*)d_in[2];
    const int* ptr   = (const int*)d_in[3];
    int E = in_sizes[1];
    int N = in_sizes[0] / HH;
    int G = in_sizes[3] - 1;
    float* out = (float*)d_out;

    float *agg, *z, *hA, *hB, *stats;
    int *deg, *cursor, *rowstart, *csr;
    cudaGetSymbolAddress((void**)&agg, g_agg);
    cudaGetSymbolAddress((void**)&z, g_z);
    cudaGetSymbolAddress((void**)&hA, g_hA);
    cudaGetSymbolAddress((void**)&hB, g_hB);
    cudaGetSymbolAddress((void**)&stats, g_stats);
    cudaGetSymbolAddress((void**)&deg, g_deg);
    cudaGetSymbolAddress((void**)&cursor, g_cursor);
    cudaGetSymbolAddress((void**)&rowstart, g_rowstart);
    cudaGetSymbolAddress((void**)&csr, g_csr);

    int gemm_blocks = (N + 127) / 128;
    int eb = (E + 255) / 256;
    int agg_blocks = (int)(((long long)N * 32 + 255) / 256);

    // ---- CSR build (once per call, reused by all 3 layers) ----
    cudaMemsetAsync(deg, 0, N * sizeof(int));
    cudaMemsetAsync(cursor, 0, N * sizeof(int));
    count_kernel<<<eb, 256>>>(dst, deg, E);
    scan_kernel<<<1, 1024>>>(deg, rowstart, N);
    fill_kernel<<<eb, 256>>>(src, dst, rowstart, cursor, csr, E);

    auto layer = [&](const float* hin, float* hout, int base) {
        const float* wa = (const float*)d_in[base + 0];
        const float* ba = (const float*)d_in[base + 1];
        const float* ga = (const float*)d_in[base + 2];
        const float* be = (const float*)d_in[base + 3];
        const float* wb = (const float*)d_in[base + 4];
        const float* bb = (const float*)d_in[base + 5];

        cudaMemsetAsync(stats, 0, 2 * HH * sizeof(float));
        aggregate_kernel<<<agg_blocks, 256>>>((const float4*)hin, rowstart, csr,
                                              (float4*)agg, N);
        gemm128<0><<<gemm_blocks, 256>>>(agg, wa, ba, z, N);
        finalize_kernel<<<1, 128>>>(ga, be, 1.0f / (float)N);
        gemm128<1><<<gemm_blocks, 256>>>(z, wb, bb, hout, N);
    };

    layer(x, hA, 4);
    layer(hA, hB, 10);
    layer(hB, hA, 16);

    readout_kernel<<<G, 128>>>(hA, ptr, out);
}

// round 5
// speedup vs baseline: 2.1564x; 1.2861x over previous
#include <cuda_runtime.h>
#include <cuda_bf16.h>
#include <cstdint>

#define HH 128
#define NMAX 50000
#define EMAX 800000
#define BN_EPS 1e-5f

// ---------------- scratch (no allocations allowed) ----------------
__device__ float g_agg[NMAX * HH];
__device__ float g_z[NMAX * HH];
__device__ float g_hA[NMAX * HH];
__device__ float g_hB[NMAX * HH];
__device__ float g_stats[2 * HH];   // [0:128) col sums, [128:256) col sumsq
__device__ int   g_deg[NMAX];
__device__ int   g_cursor[NMAX];
__device__ int   g_rowstart[NMAX + 1];
__device__ int   g_csr[EMAX];

// ---------------- CSR build ----------------
__global__ void count_kernel(const int* __restrict__ dst, int* __restrict__ deg, int E) {
    int e = blockIdx.x * blockDim.x + threadIdx.x;
    if (e < E) atomicAdd(&deg[dst[e]], 1);
}

__global__ void scan_kernel(const int* __restrict__ deg, int* __restrict__ rowstart, int n) {
    __shared__ int warpsum[32];
    __shared__ int s_total;
    __shared__ int s_carry;
    int tid = threadIdx.x, lane = tid & 31, wid = tid >> 5;
    if (tid == 0) s_carry = 0;
    __syncthreads();
    for (int base = 0; base < n; base += 1024) {
        int i = base + tid;
        int v = (i < n) ? deg[i] : 0;
        int incl = v;
#pragma unroll
        for (int off = 1; off < 32; off <<= 1) {
            int t = __shfl_up_sync(0xffffffff, incl, off);
            if (lane >= off) incl += t;
        }
        if (lane == 31) warpsum[wid] = incl;
        __syncthreads();
        if (wid == 0) {
            int w = warpsum[lane];
            int wincl = w;
#pragma unroll
            for (int off = 1; off < 32; off <<= 1) {
                int t = __shfl_up_sync(0xffffffff, wincl, off);
                if (lane >= off) wincl += t;
            }
            warpsum[lane] = wincl - w;
            if (lane == 31) s_total = wincl;
        }
        __syncthreads();
        int carry = s_carry;
        if (i < n) rowstart[i] = carry + warpsum[wid] + incl - v;
        __syncthreads();
        if (tid == 0) s_carry = carry + s_total;
    }
    __syncthreads();
    if (tid == 0) rowstart[n] = s_carry;
}

__global__ void fill_kernel(const int* __restrict__ src, const int* __restrict__ dst,
                            const int* __restrict__ rowstart, int* __restrict__ cursor,
                            int* __restrict__ csr, int E) {
    int e = blockIdx.x * blockDim.x + threadIdx.x;
    if (e >= E) return;
    int d = dst[e];
    int base = __ldg(&rowstart[d]);
    int p = atomicAdd(&cursor[d], 1);
    csr[base + p] = src[e];
}

// ---------------- aggregate: agg[i] = h[i] + sum_{j in N_in(i)} h[j] ---------
__global__ void aggregate_kernel(const float4* __restrict__ h,
                                 const int* __restrict__ rowstart,
                                 const int* __restrict__ csr,
                                 float4* __restrict__ agg, int N) {
    int warp = (blockIdx.x * blockDim.x + threadIdx.x) >> 5;
    int lane = threadIdx.x & 31;
    if (warp >= N) return;
    int s0 = rowstart[warp], s1 = rowstart[warp + 1];
    float4 acc = __ldg(&h[(size_t)warp * 32 + lane]);
    int j = s0;
    for (; j + 2 <= s1; j += 2) {
        int sa = __ldg(&csr[j]);
        int sb = __ldg(&csr[j + 1]);
        float4 va = __ldg(&h[(size_t)sa * 32 + lane]);
        float4 vb = __ldg(&h[(size_t)sb * 32 + lane]);
        acc.x += va.x + vb.x; acc.y += va.y + vb.y;
        acc.z += va.z + vb.z; acc.w += va.w + vb.w;
    }
    if (j < s1) {
        int sa = __ldg(&csr[j]);
        float4 va = __ldg(&h[(size_t)sa * 32 + lane]);
        acc.x += va.x; acc.y += va.y; acc.z += va.z; acc.w += va.w;
    }
    agg[(size_t)warp * 32 + lane] = acc;
}

// ---------------- HMMA GEMM (mma.sync bf16, hi/lo split) ----------------
// Shared layout: padded bf16 tiles, pitch 136 elems (272 B) -> conflict-free frags
#define APITCH 136
#define PLANE_BYTES (128 * APITCH * 2)   // 34816
#define SM_SCALE 0
#define SM_SHIFT 512
#define SM_BIAS  1024
#define SM_AHI   1536
#define SM_ALO   (SM_AHI + PLANE_BYTES)
#define SM_BHI   (SM_ALO + PLANE_BYTES)
#define SM_BLO   (SM_BHI + PLANE_BYTES)
#define SM_TOTAL (SM_BLO + PLANE_BYTES)  // 140800

__device__ __forceinline__ void mma16816(float* d, const uint32_t* a, const uint32_t* b) {
    asm volatile(
        "mma.sync.aligned.m16n8k16.row.col.f32.bf16.bf16.f32 "
        "{%0,%1,%2,%3}, {%4,%5,%6,%7}, {%8,%9}, {%0,%1,%2,%3};"
        : "+f"(d[0]), "+f"(d[1]), "+f"(d[2]), "+f"(d[3])
        : "r"(a[0]), "r"(a[1]), "r"(a[2]), "r"(a[3]), "r"(b[0]), "r"(b[1]));
}

__device__ __forceinline__ void split_bf16x2(float a0, float a1,
                                             uint32_t& hi, uint32_t& lo) {
    __nv_bfloat16 h0 = __float2bfloat16_rn(a0);
    __nv_bfloat16 h1 = __float2bfloat16_rn(a1);
    __nv_bfloat16 l0 = __float2bfloat16_rn(a0 - __bfloat162float(h0));
    __nv_bfloat16 l1 = __float2bfloat16_rn(a1 - __bfloat162float(h1));
    hi = (uint32_t)__bfloat16_as_ushort(h0) | ((uint32_t)__bfloat16_as_ushort(h1) << 16);
    lo = (uint32_t)__bfloat16_as_ushort(l0) | ((uint32_t)__bfloat16_as_ushort(l1) << 16);
}

// MODE 0: out = A@W + bias (stores z); fused BN column stats -> g_stats
// MODE 1: A' = relu(A*scale+shift), scale/shift from g_stats (fused finalize);
//         out = relu(A'@W + bias)
template <int MODE>
__global__ __launch_bounds__(256, 1) void gemm_mma(
    const float* __restrict__ A, const float* __restrict__ W,
    const float* __restrict__ bias, const float* __restrict__ gamma,
    const float* __restrict__ beta, float inv_n,
    float* __restrict__ out, int nrows) {
    extern __shared__ char smem[];
    int tid = threadIdx.x;
    int lane = tid & 31;
    int wid = tid >> 5;
    int groupID = lane >> 2;
    int tig = lane & 3;
    int warp_m = wid & 1;     // 0..1 -> 64 rows each
    int warp_n = wid >> 1;    // 0..3 -> 32 cols each
    int block_row = blockIdx.x * 128;

    float* sh_scale = (float*)(smem + SM_SCALE);
    float* sh_shift = (float*)(smem + SM_SHIFT);
    float* sh_bias  = (float*)(smem + SM_BIAS);

    if (tid < 128) {
        sh_bias[tid] = bias[tid];
        if (MODE == 1) {
            float mu = g_stats[tid] * inv_n;
            float var = fmaf(-mu, mu, g_stats[128 + tid] * inv_n);
            float rs = rsqrtf(var + BN_EPS);
            float sc = gamma[tid] * rs;
            sh_scale[tid] = sc;
            sh_shift[tid] = fmaf(-mu, sc, beta[tid]);
        }
    }
    __syncthreads();

    // ---- A tile: 128 rows x 128 cols fp32 -> hi/lo bf16, padded row-major ----
    {
        int r = tid >> 1, half = tid & 1;
        int grow = block_row + r;
        const float4* arow =
            reinterpret_cast<const float4*>(A + (size_t)grow * HH + half * 64);
        uint32_t dbase = (uint32_t)r * (APITCH * 2) + half * 128;
#pragma unroll
        for (int i = 0; i < 8; i++) {
            float v[8];
            if (grow < nrows) {
                float4 p0 = arow[2 * i], p1 = arow[2 * i + 1];
                v[0] = p0.x; v[1] = p0.y; v[2] = p0.z; v[3] = p0.w;
                v[4] = p1.x; v[5] = p1.y; v[6] = p1.z; v[7] = p1.w;
                if (MODE == 1) {
                    int c0 = half * 64 + i * 8;
#pragma unroll
                    for (int j = 0; j < 8; j++)
                        v[j] = fmaxf(fmaf(v[j], sh_scale[c0 + j], sh_shift[c0 + j]), 0.f);
                }
            } else {
#pragma unroll
                for (int j = 0; j < 8; j++) v[j] = 0.f;
            }
            uint32_t hi[4], lo[4];
#pragma unroll
            for (int j = 0; j < 4; j++)
                split_bf16x2(v[2 * j], v[2 * j + 1], hi[j], lo[j]);
            uint32_t off = dbase + i * 16;
            *reinterpret_cast<uint4*>(smem + SM_AHI + off) =
                make_uint4(hi[0], hi[1], hi[2], hi[3]);
            *reinterpret_cast<uint4*>(smem + SM_ALO + off) =
                make_uint4(lo[0], lo[1], lo[2], lo[3]);
        }
    }
    // ---- B tile: Bs[n][k] = W[k][n] (transpose), hi/lo planes ----
    {
        int k = tid >> 1, half = tid & 1;
        const float4* wrow =
            reinterpret_cast<const float4*>(W + (size_t)k * HH + half * 64);
#pragma unroll
        for (int i = 0; i < 16; i++) {
            float4 p = wrow[i];
            float vv[4] = {p.x, p.y, p.z, p.w};
#pragma unroll
            for (int j = 0; j < 4; j++) {
                int n = half * 64 + i * 4 + j;
                __nv_bfloat16 h = __float2bfloat16_rn(vv[j]);
                __nv_bfloat16 l = __float2bfloat16_rn(vv[j] - __bfloat162float(h));
                uint32_t off = (uint32_t)n * (APITCH * 2) + k * 2;
                *(uint16_t*)(smem + SM_BHI + off) = __bfloat16_as_ushort(h);
                *(uint16_t*)(smem + SM_BLO + off) = __bfloat16_as_ushort(l);
            }
        }
    }
    __syncthreads();

    // ---- mainloop: 8 k-steps of 16; 3 terms (hh, hl, lh) ----
    float acc[4][4][4] = {};
#pragma unroll
    for (int ks = 0; ks < 8; ks++) {
        uint32_t kb = (uint32_t)ks * 32 + tig * 4;  // byte offset within row
        uint32_t ah[4][4], al[4][4], bh[4][2], bl[4][2];
#pragma unroll
        for (int mf = 0; mf < 4; mf++) {
            uint32_t base = (uint32_t)(warp_m * 64 + mf * 16 + groupID) * (APITCH * 2) + kb;
            ah[mf][0] = *(const uint32_t*)(smem + SM_AHI + base);
            ah[mf][1] = *(const uint32_t*)(smem + SM_AHI + base + 8 * APITCH * 2);
            ah[mf][2] = *(const uint32_t*)(smem + SM_AHI + base + 16);
            ah[mf][3] = *(const uint32_t*)(smem + SM_AHI + base + 8 * APITCH * 2 + 16);
            al[mf][0] = *(const uint32_t*)(smem + SM_ALO + base);
            al[mf][1] = *(const uint32_t*)(smem + SM_ALO + base + 8 * APITCH * 2);
            al[mf][2] = *(const uint32_t*)(smem + SM_ALO + base + 16);
            al[mf][3] = *(const uint32_t*)(smem + SM_ALO + base + 8 * APITCH * 2 + 16);
        }
#pragma unroll
        for (int nf = 0; nf < 4; nf++) {
            uint32_t base = (uint32_t)(warp_n * 32 + nf * 8 + groupID) * (APITCH * 2) + kb;
            bh[nf][0] = *(const uint32_t*)(smem + SM_BHI + base);
            bh[nf][1] = *(const uint32_t*)(smem + SM_BHI + base + 16);
            bl[nf][0] = *(const uint32_t*)(smem + SM_BLO + base);
            bl[nf][1] = *(const uint32_t*)(smem + SM_BLO + base + 16);
        }
#pragma unroll
        for (int mf = 0; mf < 4; mf++)
#pragma unroll
            for (int nf = 0; nf < 4; nf++) {
                mma16816(acc[mf][nf], ah[mf], bh[nf]);
                mma16816(acc[mf][nf], ah[mf], bl[nf]);
                mma16816(acc[mf][nf], al[mf], bh[nf]);
            }
    }

    // ---- epilogue: bias (+relu), store, stats (MODE 0) ----
    float cs[4][2] = {}, cq[4][2] = {};
#pragma unroll
    for (int mf = 0; mf < 4; mf++) {
        int r0 = block_row + warp_m * 64 + mf * 16 + groupID;
        int r1 = r0 + 8;
#pragma unroll
        for (int nf = 0; nf < 4; nf++) {
            int c0 = warp_n * 32 + nf * 8 + 2 * tig;
            float b0 = sh_bias[c0], b1 = sh_bias[c0 + 1];
            float t00 = acc[mf][nf][0] + b0, t01 = acc[mf][nf][1] + b1;
            float t10 = acc[mf][nf][2] + b0, t11 = acc[mf][nf][3] + b1;
            if (MODE == 1) {
                t00 = fmaxf(t00, 0.f); t01 = fmaxf(t01, 0.f);
                t10 = fmaxf(t10, 0.f); t11 = fmaxf(t11, 0.f);
            }
            if (r0 < nrows) {
                *reinterpret_cast<float2*>(out + (size_t)r0 * HH + c0) =
                    make_float2(t00, t01);
                if (MODE == 0) {
                    cs[nf][0] += t00; cq[nf][0] = fmaf(t00, t00, cq[nf][0]);
                    cs[nf][1] += t01; cq[nf][1] = fmaf(t01, t01, cq[nf][1]);
                }
            }
            if (r1 < nrows) {
                *reinterpret_cast<float2*>(out + (size_t)r1 * HH + c0) =
                    make_float2(t10, t11);
                if (MODE == 0) {
                    cs[nf][0] += t10; cq[nf][0] = fmaf(t10, t10, cq[nf][0]);
                    cs[nf][1] += t11; cq[nf][1] = fmaf(t11, t11, cq[nf][1]);
                }
            }
        }
    }
    if (MODE == 0) {
        // reduce across groupID (lanes stride 4), then lanes 0..3 hold col sums
#pragma unroll
        for (int nf = 0; nf < 4; nf++)
#pragma unroll
            for (int j = 0; j < 2; j++) {
                float s = cs[nf][j], q = cq[nf][j];
#pragma unroll
                for (int off = 16; off >= 4; off >>= 1) {
                    s += __shfl_down_sync(0xffffffff, s, off);
                    q += __shfl_down_sync(0xffffffff, q, off);
                }
                if (lane < 4) {
                    int col = warp_n * 32 + nf * 8 + 2 * lane + j;
                    atomicAdd(&g_stats[col], s);
                    atomicAdd(&g_stats[128 + col], q);
                }
            }
    }
}

// ---------------- segment-CSR readout ----------------
__global__ void readout_kernel(const float* __restrict__ h,
                               const int* __restrict__ ptr,
                               float* __restrict__ out) {
    int g = blockIdx.x;
    int c = threadIdx.x;
    int s = ptr[g], e = ptr[g + 1];
    float acc = 0.f;
    for (int r = s; r < e; r++) acc += h[r * HH + c];
    out[g * HH + c] = acc;
}

// ---------------- host launch ----------------
extern "C" void kernel_launch(void* const* d_in, const int* in_sizes, int n_in,
                              void* d_out, int out_size) {
    const float* x = (const float*)d_in[0];
    const int* src = (const int*)d_in[1];
    const int* dst = (const int*)d_in[2];
    const int* ptr = (const int*)d_in[3];
    int E = in_sizes[1];
    int N = in_sizes[0] / HH;
    int G = in_sizes[3] - 1;
    float* out = (float*)d_out;

    float *agg, *z, *hA, *hB, *stats;
    int *deg, *cursor, *rowstart, *csr;
    cudaGetSymbolAddress((void**)&agg, g_agg);
    cudaGetSymbolAddress((void**)&z, g_z);
    cudaGetSymbolAddress((void**)&hA, g_hA);
    cudaGetSymbolAddress((void**)&hB, g_hB);
    cudaGetSymbolAddress((void**)&stats, g_stats);
    cudaGetSymbolAddress((void**)&deg, g_deg);
    cudaGetSymbolAddress((void**)&cursor, g_cursor);
    cudaGetSymbolAddress((void**)&rowstart, g_rowstart);
    cudaGetSymbolAddress((void**)&csr, g_csr);

    cudaFuncSetAttribute(gemm_mma<0>, cudaFuncAttributeMaxDynamicSharedMemorySize, SM_TOTAL);
    cudaFuncSetAttribute(gemm_mma<1>, cudaFuncAttributeMaxDynamicSharedMemorySize, SM_TOTAL);

    int gemm_blocks = (N + 127) / 128;
    int eb = (E + 255) / 256;
    int agg_blocks = (int)(((long long)N * 32 + 255) / 256);
    float inv_n = 1.0f / (float)N;

    // ---- CSR build (once, reused by all 3 layers) ----
    cudaMemsetAsync(deg, 0, N * sizeof(int));
    cudaMemsetAsync(cursor, 0, N * sizeof(int));
    count_kernel<<<eb, 256>>>(dst, deg, E);
    scan_kernel<<<1, 1024>>>(deg, rowstart, N);
    fill_kernel<<<eb, 256>>>(src, dst, rowstart, cursor, csr, E);

    auto layer = [&](const float* hin, float* hout, int base) {
        const float* wa = (const float*)d_in[base + 0];
        const float* ba = (const float*)d_in[base + 1];
        const float* ga = (const float*)d_in[base + 2];
        const float* be = (const float*)d_in[base + 3];
        const float* wb = (const float*)d_in[base + 4];
        const float* bb = (const float*)d_in[base + 5];

        cudaMemsetAsync(stats, 0, 2 * HH * sizeof(float));
        aggregate_kernel<<<agg_blocks, 256>>>((const float4*)hin, rowstart, csr,
                                              (float4*)agg, N);
        gemm_mma<0><<<gemm_blocks, 256, SM_TOTAL>>>(agg, wa, ba, nullptr, nullptr,
                                                    0.f, z, N);
        gemm_mma<1><<<gemm_blocks, 256, SM_TOTAL>>>(z, wb, bb, ga, be,
                                                    inv_n, hout, N);
    };

    layer(x, hA, 4);
    layer(hA, hB, 10);
    layer(hB, hA, 16);

    readout_kernel<<<G, 128>>>(hA, ptr, out);
}